// round 10
// baseline (speedup 1.0000x reference)
#include <cuda_runtime.h>
#include <cuda_bf16.h>
#include <cstdint>

// WindowAttention round 10: 512-thread HMMA GEMMs (16 warps, 8Mx2N warp grid),
// cp.async double-buffered pre-converted weights, float4 attention staging.
// K0: weight prep ; K1: qkv_gemm ; K2: attention ; K3: proj_gemm

namespace {
constexpr int MTOT = 200704;
constexpr float QSCALE = 0.17677669529663687f;

constexpr int A_HI = 0;                       // 128 x 400 B
constexpr int A_LO = 51200;
constexpr int B_BUF0 = 102400;                // each buf: hi 64x400, lo 64x400
constexpr int B_BUF_SZ = 51200;
constexpr int GEMM_SMEM = 204800;
constexpr int GT = 512;                       // GEMM threads

constexpr int AQ = 0;
constexpr int AK = 4704;
constexpr int AV = 9408;
constexpr int AS = 14112;
constexpr int AO = 21315;
constexpr int ATTN_FLOATS = 26068;            // 104272 B -> 2 CTAs/SM
}

__device__ __align__(16) float g_qkv[(size_t)MTOT * 576];
__device__ __align__(16) float g_so[(size_t)MTOT * 192];
__device__ __align__(16) unsigned short g_wqh[576 * 192];
__device__ __align__(16) unsigned short g_wql[576 * 192];
__device__ __align__(16) unsigned short g_wph[192 * 192];
__device__ __align__(16) unsigned short g_wpl[192 * 192];

__device__ __forceinline__ uint32_t smem_u32(const void* p) {
    uint32_t a;
    asm("{ .reg .u64 t; cvta.to.shared.u64 t, %1; cvt.u32.u64 %0, t; }" : "=r"(a) : "l"(p));
    return a;
}
__device__ __forceinline__ void cp16(uint32_t dst, const void* src) {
    asm volatile("cp.async.cg.shared.global [%0], [%1], 16;" :: "r"(dst), "l"(src));
}
#define CP_COMMIT() asm volatile("cp.async.commit_group;" ::: "memory")
#define CP_WAIT(n)  asm volatile("cp.async.wait_group %0;" :: "n"(n) : "memory")

__device__ __forceinline__ void ldmx4(uint32_t& r0, uint32_t& r1, uint32_t& r2, uint32_t& r3,
                                      uint32_t addr) {
    asm volatile("ldmatrix.sync.aligned.m8n8.x4.shared.b16 {%0,%1,%2,%3}, [%4];"
                 : "=r"(r0), "=r"(r1), "=r"(r2), "=r"(r3) : "r"(addr));
}
__device__ __forceinline__ void mma16816(float* c, uint32_t a0, uint32_t a1, uint32_t a2,
                                         uint32_t a3, uint32_t b0, uint32_t b1) {
    asm volatile("mma.sync.aligned.m16n8k16.row.col.f32.bf16.bf16.f32 "
                 "{%0,%1,%2,%3}, {%4,%5,%6,%7}, {%8,%9}, {%0,%1,%2,%3};"
                 : "+f"(c[0]), "+f"(c[1]), "+f"(c[2]), "+f"(c[3])
                 : "r"(a0), "r"(a1), "r"(a2), "r"(a3), "r"(b0), "r"(b1));
}

// fp32 [128,192] -> bf16 hi/lo padded rows (stride 400 B)
__device__ __forceinline__ void stage_split_A(const float* __restrict__ gsrc,
                                              char* shi, char* slo, int tid) {
    for (int p = tid; p < 128 * 96; p += GT) {
        const int r = p / 96, kp = p - r * 96;
        const float2 v = *reinterpret_cast<const float2*>(gsrc + (size_t)r * 192 + 2 * kp);
        const __nv_bfloat16 h0 = __float2bfloat16(v.x);
        const __nv_bfloat16 h1 = __float2bfloat16(v.y);
        const __nv_bfloat16 l0 = __float2bfloat16(v.x - __bfloat162float(h0));
        const __nv_bfloat16 l1 = __float2bfloat16(v.y - __bfloat162float(h1));
        const uint32_t hi = ((uint32_t)__bfloat16_as_ushort(h1) << 16) | __bfloat16_as_ushort(h0);
        const uint32_t lo = ((uint32_t)__bfloat16_as_ushort(l1) << 16) | __bfloat16_as_ushort(l0);
        const uint32_t off = (uint32_t)r * 400u + (uint32_t)kp * 4u;
        *reinterpret_cast<uint32_t*>(shi + off) = hi;
        *reinterpret_cast<uint32_t*>(slo + off) = lo;
    }
}

__device__ __forceinline__ void prefetch_B(const unsigned short* wh, const unsigned short* wl,
                                           int nt, uint32_t dhi, uint32_t dlo, int tid) {
    for (int c = tid; c < 64 * 24; c += GT) {
        const int r = c / 24, k = c - r * 24;
        const uint32_t d = (uint32_t)r * 400u + (uint32_t)k * 16u;
        cp16(dhi + d, (const char*)(wh + (size_t)(nt * 64 + r) * 192) + k * 16);
        cp16(dlo + d, (const char*)(wl + (size_t)(nt * 64 + r) * 192) + k * 16);
    }
}

// Per-warp 16x32 tile: 36 k-steps of hi*hi + hi*lo + lo*hi -> c[4][4]
__device__ __forceinline__ void mma_tile(float (*c)[4], uint32_t ahi, uint32_t alo,
                                         uint32_t bhi, uint32_t blo) {
    #pragma unroll
    for (int split = 0; split < 3; ++split) {
        const uint32_t abase = (split == 2) ? alo : ahi;
        const uint32_t bbase = (split == 1) ? blo : bhi;
        #pragma unroll
        for (int ks = 0; ks < 12; ++ks) {
            uint32_t a0, a1, a2, a3;
            ldmx4(a0, a1, a2, a3, abase + ks * 32);
            #pragma unroll
            for (int p2 = 0; p2 < 2; ++p2) {
                uint32_t b0, b1, b2, b3;
                ldmx4(b0, b1, b2, b3, bbase + p2 * 6400 + ks * 32);
                mma16816(c[2 * p2],     a0, a1, a2, a3, b0, b1);
                mma16816(c[2 * p2 + 1], a0, a1, a2, a3, b2, b3);
            }
        }
    }
}

// ---------------- K0: weight prep ----------------
__global__ __launch_bounds__(256)
void prep_kernel(const float* __restrict__ qkv_w, const float* __restrict__ proj_w) {
    const int idx = blockIdx.x * 256 + threadIdx.x;
    if (idx < 576 * 192) {
        const float v = qkv_w[idx];
        const __nv_bfloat16 h = __float2bfloat16(v);
        g_wqh[idx] = __bfloat16_as_ushort(h);
        g_wql[idx] = __bfloat16_as_ushort(__float2bfloat16(v - __bfloat162float(h)));
    }
    if (idx < 192 * 192) {
        const float v = proj_w[idx];
        const __nv_bfloat16 h = __float2bfloat16(v);
        g_wph[idx] = __bfloat16_as_ushort(h);
        g_wpl[idx] = __bfloat16_as_ushort(__float2bfloat16(v - __bfloat162float(h)));
    }
}

// ---------------- K1: QKV GEMM ----------------
__global__ __launch_bounds__(GT, 1)
void qkv_gemm_kernel(const float* __restrict__ x, const float* __restrict__ qkv_b) {
    extern __shared__ char smem[];
    const uint32_t sb = smem_u32(smem);
    const int tid = threadIdx.x, warp = tid >> 5, lane = tid & 31;
    const int wm = warp & 7, wn = warp >> 3;
    const int mtile = blockIdx.x;
    const int g = lane >> 2, tg = lane & 3;

    prefetch_B(g_wqh, g_wql, 0, sb + B_BUF0, sb + B_BUF0 + 25600, tid);
    CP_COMMIT();
    stage_split_A(x + (size_t)mtile * 128 * 192, smem + A_HI, smem + A_LO, tid);

    const uint32_t aoff = (uint32_t)(wm * 16 + (lane & 15)) * 400u + ((lane >> 4) & 1) * 16u;
    const uint32_t boff = (uint32_t)(wn * 32 + (lane & 7) + ((lane >> 4) & 1) * 8) * 400u
                        + ((lane >> 3) & 1) * 16u;
    const uint32_t ahi = sb + A_HI + aoff, alo = sb + A_LO + aoff;

    for (int nt = 0; nt < 9; ++nt) {
        const uint32_t bbase = sb + B_BUF0 + (nt & 1) * B_BUF_SZ;
        if (nt + 1 < 9) {
            prefetch_B(g_wqh, g_wql, nt + 1,
                       sb + B_BUF0 + ((nt + 1) & 1) * B_BUF_SZ,
                       sb + B_BUF0 + ((nt + 1) & 1) * B_BUF_SZ + 25600, tid);
            CP_COMMIT();
            CP_WAIT(1);
        } else {
            CP_WAIT(0);
        }
        __syncthreads();

        float c[4][4];
        #pragma unroll
        for (int i = 0; i < 4; ++i)
            #pragma unroll
            for (int j = 0; j < 4; ++j) c[i][j] = 0.f;

        mma_tile(c, ahi, alo, bbase + boff, bbase + 25600 + boff);

        const size_t mbase = (size_t)mtile * 128 + wm * 16;
        #pragma unroll
        for (int p2 = 0; p2 < 2; ++p2) {
            #pragma unroll
            for (int half = 0; half < 2; ++half) {
                const float* cc = c[2 * p2 + half];
                const int n = nt * 64 + wn * 32 + p2 * 16 + half * 8 + tg * 2;
                const float b0 = __ldg(qkv_b + n);
                const float b1 = __ldg(qkv_b + n + 1);
                const float s = (n < 192) ? QSCALE : 1.f;
                *reinterpret_cast<float2*>(&g_qkv[(mbase + g) * 576 + n]) =
                    make_float2((cc[0] + b0) * s, (cc[1] + b1) * s);
                *reinterpret_cast<float2*>(&g_qkv[(mbase + g + 8) * 576 + n]) =
                    make_float2((cc[2] + b0) * s, (cc[3] + b1) * s);
            }
        }
        __syncthreads();
    }
}

// ---------------- K2: attention ----------------
__global__ __launch_bounds__(256, 2)
void attn_kernel(const float* __restrict__ mask,
                 const float* __restrict__ bias_table,
                 const int* __restrict__ rel_index) {
    extern __shared__ float sf[];
    float* sq = sf + AQ;
    float* sk = sf + AK;
    float* sv = sf + AV;
    float* sa = sf + AS;
    float* so = sf + AO;

    const int tid = threadIdx.x, warp = tid >> 5, lane = tid & 31;
    const int win = blockIdx.x >> 1;
    const int hg  = blockIdx.x & 1;
    const int w   = win & 63;

    // float4 loads, perfectly coalesced; smem scatter stride 49 (CF)
    for (int idx = tid; idx < 3 * 49 * 24; idx += 256) {
        const int mat = idx / (49 * 24);
        const int rem = idx - mat * (49 * 24);
        const int tok = rem / 24, rq = rem - tok * 24;
        const float4 v = __ldg(reinterpret_cast<const float4*>(
            &g_qkv[((size_t)win * 49 + tok) * 576 + mat * 192 + hg * 96 + rq * 4]));
        const int base = mat * 4704 + rq * 4 * 49 + tok;
        sf[base]       = v.x;
        sf[base + 49]  = v.y;
        sf[base + 98]  = v.z;
        sf[base + 147] = v.w;
    }
    for (int idx = tid; idx < 3 * 2401; idx += 256) {
        const int hh = idx / 2401, rem = idx - hh * 2401;
        sa[idx] = __ldg(bias_table + __ldg(rel_index + rem) * 6 + hg * 3 + hh)
                + __ldg(mask + (size_t)w * 2401 + rem);
    }
    __syncthreads();

    for (int rowid = warp; rowid < 147; rowid += 8) {
        const int hh = rowid / 49, i = rowid - hh * 49;
        const float* qc = sq + hh * 1568 + i;
        const float* kr = sk + hh * 1568;
        float a0 = 0.f, a1 = 0.f;
        #pragma unroll 8
        for (int d = 0; d < 32; ++d) {
            const float qv = qc[d * 49];
            a0 += qv * kr[d * 49 + lane];
            a1 += qv * kr[d * 49 + lane + 32];
        }
        float* prow = sa + rowid * 49;
        prow[lane] += a0;
        if (lane < 17) prow[lane + 32] += a1;
    }
    __syncthreads();

    if (tid < 147) {
        float* p = sa + tid * 49;
        float m = -1e30f;
        #pragma unroll 7
        for (int j = 0; j < 49; ++j) m = fmaxf(m, p[j]);
        float sum = 0.f;
        #pragma unroll 7
        for (int j = 0; j < 49; ++j) { const float e = __expf(p[j] - m); p[j] = e; sum += e; }
        const float inv = __frcp_rn(sum);
        #pragma unroll 7
        for (int j = 0; j < 49; ++j) p[j] *= inv;
    }
    __syncthreads();

    for (int task = warp; task < 96; task += 8) {
        const int hh = task >> 5, d = task & 31;
        const float* ab = sa + hh * 2401;
        const float* vr = sv + hh * 1568 + d * 49;
        float a0 = 0.f, a1 = 0.f;
        #pragma unroll 7
        for (int j = 0; j < 49; ++j) {
            const float vv = vr[j];
            a0 += ab[lane * 49 + j] * vv;
            a1 += ab[(lane + 32) * 49 + j] * vv;
        }
        so[lane * 97 + hh * 32 + d] = a0;
        if (lane < 17) so[(lane + 32) * 97 + hh * 32 + d] = a1;
    }
    __syncthreads();

    for (int idx = tid; idx < 49 * 96; idx += 256) {
        const int i = idx / 96, c = idx - i * 96;
        g_so[((size_t)win * 49 + i) * 192 + hg * 96 + c] = so[i * 97 + c];
    }
}

// ---------------- K3: proj GEMM ----------------
__global__ __launch_bounds__(GT, 1)
void proj_gemm_kernel(const float* __restrict__ proj_b, float* __restrict__ out) {
    extern __shared__ char smem[];
    const uint32_t sb = smem_u32(smem);
    const int tid = threadIdx.x, warp = tid >> 5, lane = tid & 31;
    const int wm = warp & 7, wn = warp >> 3;
    const int mtile = blockIdx.x;
    const int g = lane >> 2, tg = lane & 3;

    prefetch_B(g_wph, g_wpl, 0, sb + B_BUF0, sb + B_BUF0 + 25600, tid);
    CP_COMMIT();
    stage_split_A(g_so + (size_t)mtile * 128 * 192, smem + A_HI, smem + A_LO, tid);

    const uint32_t aoff = (uint32_t)(wm * 16 + (lane & 15)) * 400u + ((lane >> 4) & 1) * 16u;
    const uint32_t boff = (uint32_t)(wn * 32 + (lane & 7) + ((lane >> 4) & 1) * 8) * 400u
                        + ((lane >> 3) & 1) * 16u;
    const uint32_t ahi = sb + A_HI + aoff, alo = sb + A_LO + aoff;

    for (int nt = 0; nt < 3; ++nt) {
        const uint32_t bbase = sb + B_BUF0 + (nt & 1) * B_BUF_SZ;
        if (nt + 1 < 3) {
            prefetch_B(g_wph, g_wpl, nt + 1,
                       sb + B_BUF0 + ((nt + 1) & 1) * B_BUF_SZ,
                       sb + B_BUF0 + ((nt + 1) & 1) * B_BUF_SZ + 25600, tid);
            CP_COMMIT();
            CP_WAIT(1);
        } else {
            CP_WAIT(0);
        }
        __syncthreads();

        float c[4][4];
        #pragma unroll
        for (int i = 0; i < 4; ++i)
            #pragma unroll
            for (int j = 0; j < 4; ++j) c[i][j] = 0.f;

        mma_tile(c, ahi, alo, bbase + boff, bbase + 25600 + boff);

        const size_t mbase = (size_t)mtile * 128 + wm * 16;
        #pragma unroll
        for (int p2 = 0; p2 < 2; ++p2) {
            #pragma unroll
            for (int half = 0; half < 2; ++half) {
                const float* cc = c[2 * p2 + half];
                const int n = nt * 64 + wn * 32 + p2 * 16 + half * 8 + tg * 2;
                const float b0 = __ldg(proj_b + n);
                const float b1 = __ldg(proj_b + n + 1);
                *reinterpret_cast<float2*>(&out[(mbase + g) * 192 + n]) =
                    make_float2(cc[0] + b0, cc[1] + b1);
                *reinterpret_cast<float2*>(&out[(mbase + g + 8) * 192 + n]) =
                    make_float2(cc[2] + b0, cc[3] + b1);
            }
        }
        __syncthreads();
    }
}

extern "C" void kernel_launch(void* const* d_in, const int* in_sizes, int n_in,
                              void* d_out, int out_size) {
    const float* x          = (const float*)d_in[0];
    const float* mask       = (const float*)d_in[1];
    const float* qkv_w      = (const float*)d_in[2];
    const float* qkv_b      = (const float*)d_in[3];
    const float* proj_w     = (const float*)d_in[4];
    const float* proj_b     = (const float*)d_in[5];
    const float* bias_table = (const float*)d_in[6];
    const int*   rel_index  = (const int*)d_in[7];
    (void)in_sizes; (void)n_in; (void)out_size;

    cudaFuncSetAttribute(qkv_gemm_kernel,  cudaFuncAttributeMaxDynamicSharedMemorySize, GEMM_SMEM);
    cudaFuncSetAttribute(proj_gemm_kernel, cudaFuncAttributeMaxDynamicSharedMemorySize, GEMM_SMEM);
    cudaFuncSetAttribute(attn_kernel,      cudaFuncAttributeMaxDynamicSharedMemorySize, ATTN_FLOATS * 4);

    prep_kernel<<<432, 256>>>(qkv_w, proj_w);
    qkv_gemm_kernel<<<1568, GT, GEMM_SMEM>>>(x, qkv_b);
    attn_kernel<<<8192, 256, ATTN_FLOATS * 4>>>(mask, bias_table, rel_index);
    proj_gemm_kernel<<<1568, GT, GEMM_SMEM>>>(proj_b, (float*)d_out);
}

// round 15
// speedup vs baseline: 1.4114x; 1.4114x over previous
#include <cuda_runtime.h>
#include <cuda_bf16.h>
#include <cstdint>

// WindowAttention v15: R11 design with the misaligned-so4 bug fixed (AO 21903->21904).
// wa_prep -> wa_qkv -> wa_attn -> wa_proj

namespace {
constexpr int MTOT = 200704;
constexpr float QSCALE = 0.17677669529663687f;

constexpr int A_HI = 0;                       // 128 x 400 B
constexpr int A_LO = 51200;
constexpr int B_BUF0 = 102400;
constexpr int B_BUF_SZ = 51200;
constexpr int GEMM_SMEM = 204800;
constexpr int GT = 512;

constexpr int AQ = 0;                         // [3][49][32]
constexpr int AK = 4704;                      // [3][49][36]
constexpr int AV = 9996;                      // [3][49][32]
constexpr int AS = 14700;                     // [3][49][49] = 7203
constexpr int AO = 21904;                     // [49][100]  (16B-aligned float4 base!)
constexpr int ATTN_FLOATS = 26804;            // 107216 B
static_assert(AO % 4 == 0 && AV % 4 == 0 && AK % 4 == 0, "float4 bases must be 16B aligned");
}

__device__ __align__(16) float g_buf_qkv[(size_t)MTOT * 576];
__device__ __align__(16) float g_buf_so[(size_t)MTOT * 192];
__device__ __align__(16) unsigned short g_qw_hi[576 * 192];
__device__ __align__(16) unsigned short g_qw_lo[576 * 192];
__device__ __align__(16) unsigned short g_pw_hi[192 * 192];
__device__ __align__(16) unsigned short g_pw_lo[192 * 192];

__device__ __forceinline__ uint32_t smem_u32(const void* p) {
    uint32_t a;
    asm("{ .reg .u64 t; cvta.to.shared.u64 t, %1; cvt.u32.u64 %0, t; }" : "=r"(a) : "l"(p));
    return a;
}
__device__ __forceinline__ void cp16(uint32_t dst, const void* src) {
    asm volatile("cp.async.cg.shared.global [%0], [%1], 16;" :: "r"(dst), "l"(src));
}
#define CP_COMMIT() asm volatile("cp.async.commit_group;" ::: "memory")
#define CP_WAIT(n)  asm volatile("cp.async.wait_group %0;" :: "n"(n) : "memory")

__device__ __forceinline__ void ldmx4(uint32_t& r0, uint32_t& r1, uint32_t& r2, uint32_t& r3,
                                      uint32_t addr) {
    asm volatile("ldmatrix.sync.aligned.m8n8.x4.shared.b16 {%0,%1,%2,%3}, [%4];"
                 : "=r"(r0), "=r"(r1), "=r"(r2), "=r"(r3) : "r"(addr));
}
__device__ __forceinline__ void mma16816(float* c, uint32_t a0, uint32_t a1, uint32_t a2,
                                         uint32_t a3, uint32_t b0, uint32_t b1) {
    asm volatile("mma.sync.aligned.m16n8k16.row.col.f32.bf16.bf16.f32 "
                 "{%0,%1,%2,%3}, {%4,%5,%6,%7}, {%8,%9}, {%0,%1,%2,%3};"
                 : "+f"(c[0]), "+f"(c[1]), "+f"(c[2]), "+f"(c[3])
                 : "r"(a0), "r"(a1), "r"(a2), "r"(a3), "r"(b0), "r"(b1));
}

__device__ __forceinline__ void stage_act(const float* __restrict__ gsrc,
                                          char* shi, char* slo, int tid) {
    for (int p = tid; p < 128 * 96; p += GT) {
        const int r = p / 96;
        const int kp = p - r * 96;
        const float2 v = *reinterpret_cast<const float2*>(gsrc + (size_t)r * 192 + 2 * kp);
        const __nv_bfloat16 h0 = __float2bfloat16(v.x);
        const __nv_bfloat16 h1 = __float2bfloat16(v.y);
        const __nv_bfloat16 l0 = __float2bfloat16(v.x - __bfloat162float(h0));
        const __nv_bfloat16 l1 = __float2bfloat16(v.y - __bfloat162float(h1));
        const uint32_t hi = ((uint32_t)__bfloat16_as_ushort(h1) << 16) | __bfloat16_as_ushort(h0);
        const uint32_t lo = ((uint32_t)__bfloat16_as_ushort(l1) << 16) | __bfloat16_as_ushort(l0);
        const uint32_t off = (uint32_t)r * 400u + (uint32_t)kp * 4u;
        *reinterpret_cast<uint32_t*>(shi + off) = hi;
        *reinterpret_cast<uint32_t*>(slo + off) = lo;
    }
}

__device__ __forceinline__ void fetch_w(const unsigned short* wh, const unsigned short* wl,
                                        int nt, uint32_t dhi, uint32_t dlo, int tid) {
    for (int c = tid; c < 64 * 24; c += GT) {
        const int r = c / 24;
        const int k = c - r * 24;
        const uint32_t d = (uint32_t)r * 400u + (uint32_t)k * 16u;
        cp16(dhi + d, (const char*)(wh + (size_t)(nt * 64 + r) * 192) + k * 16);
        cp16(dlo + d, (const char*)(wl + (size_t)(nt * 64 + r) * 192) + k * 16);
    }
}

__device__ __forceinline__ void warp_mma(float (*c)[4], uint32_t ahi, uint32_t alo,
                                         uint32_t bhi, uint32_t blo) {
    #pragma unroll
    for (int ks = 0; ks < 12; ++ks) {
        uint32_t ah0, ah1, ah2, ah3, al0, al1, al2, al3;
        ldmx4(ah0, ah1, ah2, ah3, ahi + ks * 32);
        ldmx4(al0, al1, al2, al3, alo + ks * 32);
        #pragma unroll
        for (int p2 = 0; p2 < 2; ++p2) {
            uint32_t bh0, bh1, bh2, bh3, bl0, bl1, bl2, bl3;
            ldmx4(bh0, bh1, bh2, bh3, bhi + p2 * 6400 + ks * 32);
            ldmx4(bl0, bl1, bl2, bl3, blo + p2 * 6400 + ks * 32);
            mma16816(c[2 * p2],     ah0, ah1, ah2, ah3, bh0, bh1);
            mma16816(c[2 * p2 + 1], ah0, ah1, ah2, ah3, bh2, bh3);
            mma16816(c[2 * p2],     ah0, ah1, ah2, ah3, bl0, bl1);
            mma16816(c[2 * p2 + 1], ah0, ah1, ah2, ah3, bl2, bl3);
            mma16816(c[2 * p2],     al0, al1, al2, al3, bh0, bh1);
            mma16816(c[2 * p2 + 1], al0, al1, al2, al3, bh2, bh3);
        }
    }
}

// ---------------- wa_prep ----------------
__global__ __launch_bounds__(256)
void wa_prep(const float* __restrict__ qkv_w, const float* __restrict__ proj_w) {
    const int idx = blockIdx.x * 256 + threadIdx.x;
    if (idx < 576 * 192) {
        const float v = qkv_w[idx];
        const __nv_bfloat16 h = __float2bfloat16(v);
        g_qw_hi[idx] = __bfloat16_as_ushort(h);
        g_qw_lo[idx] = __bfloat16_as_ushort(__float2bfloat16(v - __bfloat162float(h)));
    }
    if (idx < 192 * 192) {
        const float v = proj_w[idx];
        const __nv_bfloat16 h = __float2bfloat16(v);
        g_pw_hi[idx] = __bfloat16_as_ushort(h);
        g_pw_lo[idx] = __bfloat16_as_ushort(__float2bfloat16(v - __bfloat162float(h)));
    }
}

// ---------------- wa_qkv ----------------
__global__ __launch_bounds__(GT, 1)
void wa_qkv(const float* __restrict__ x, const float* __restrict__ qkv_b) {
    extern __shared__ char smem[];
    const uint32_t sb = smem_u32(smem);
    const int tid = threadIdx.x;
    const int warp = tid >> 5, lane = tid & 31;
    const int wm = warp & 7, wn = warp >> 3;
    const int mtile = blockIdx.x;
    const int g = lane >> 2, tg = lane & 3;

    fetch_w(g_qw_hi, g_qw_lo, 0, sb + B_BUF0, sb + B_BUF0 + 25600, tid);
    CP_COMMIT();
    stage_act(x + (size_t)mtile * 128 * 192, smem + A_HI, smem + A_LO, tid);

    const uint32_t aoff = (uint32_t)(wm * 16 + (lane & 15)) * 400u + ((lane >> 4) & 1) * 16u;
    const uint32_t boff = (uint32_t)(wn * 32 + (lane & 7) + ((lane >> 4) & 1) * 8) * 400u
                        + ((lane >> 3) & 1) * 16u;
    const uint32_t ahi = sb + A_HI + aoff;
    const uint32_t alo = sb + A_LO + aoff;

    for (int nt = 0; nt < 9; ++nt) {
        const uint32_t bbase = sb + B_BUF0 + (nt & 1) * B_BUF_SZ;
        if (nt + 1 < 9) {
            const uint32_t nb = sb + B_BUF0 + ((nt + 1) & 1) * B_BUF_SZ;
            fetch_w(g_qw_hi, g_qw_lo, nt + 1, nb, nb + 25600, tid);
            CP_COMMIT();
            CP_WAIT(1);
        } else {
            CP_WAIT(0);
        }
        __syncthreads();

        float c[4][4];
        #pragma unroll
        for (int i = 0; i < 4; ++i) { c[i][0] = 0.f; c[i][1] = 0.f; c[i][2] = 0.f; c[i][3] = 0.f; }

        warp_mma(c, ahi, alo, bbase + boff, bbase + 25600 + boff);

        const size_t mbase = (size_t)mtile * 128 + wm * 16;
        #pragma unroll
        for (int p2 = 0; p2 < 2; ++p2) {
            #pragma unroll
            for (int half = 0; half < 2; ++half) {
                const float* cc = c[2 * p2 + half];
                const int n = nt * 64 + wn * 32 + p2 * 16 + half * 8 + tg * 2;
                const float b0 = __ldg(qkv_b + n);
                const float b1 = __ldg(qkv_b + n + 1);
                const float s = (n < 192) ? QSCALE : 1.f;
                *reinterpret_cast<float2*>(&g_buf_qkv[(mbase + g) * 576 + n]) =
                    make_float2((cc[0] + b0) * s, (cc[1] + b1) * s);
                *reinterpret_cast<float2*>(&g_buf_qkv[(mbase + g + 8) * 576 + n]) =
                    make_float2((cc[2] + b0) * s, (cc[3] + b1) * s);
            }
        }
        __syncthreads();
    }
}

// ---------------- wa_attn ----------------
__global__ __launch_bounds__(256, 2)
void wa_attn(const float* __restrict__ mask,
             const float* __restrict__ bias_table,
             const int* __restrict__ rel_index) {
    extern __shared__ float sf[];
    float* sq = sf + AQ;
    float* sk = sf + AK;
    float* sv = sf + AV;
    float* sa = sf + AS;
    float4* sq4 = reinterpret_cast<float4*>(sq);
    float4* sv4 = reinterpret_cast<float4*>(sv);
    float4* so4 = reinterpret_cast<float4*>(sf + AO);

    const int tid = threadIdx.x;
    const int warp = tid >> 5, lane = tid & 31;
    const int win = blockIdx.x >> 1;
    const int hg  = blockIdx.x & 1;
    const int w   = win & 63;

    for (int idx = tid; idx < 3 * 3 * 49 * 8; idx += 256) {
        const int mat = idx / (3 * 49 * 8);
        int rem = idx - mat * (3 * 49 * 8);
        const int h = rem / (49 * 8);
        rem -= h * (49 * 8);
        const int tok = rem >> 3;
        const int d4 = rem & 7;
        const float4 v = __ldg(reinterpret_cast<const float4*>(
            &g_buf_qkv[((size_t)win * 49 + tok) * 576 + mat * 192 + (hg * 3 + h) * 32 + d4 * 4]));
        if (mat == 0)      sq4[(h * 49 + tok) * 8 + d4] = v;
        else if (mat == 1) *reinterpret_cast<float4*>(sk + (h * 49 + tok) * 36 + d4 * 4) = v;
        else               sv4[(h * 49 + tok) * 8 + d4] = v;
    }
    for (int idx = tid; idx < 3 * 2401; idx += 256) {
        const int hh = idx / 2401;
        const int rem = idx - hh * 2401;
        sa[idx] = __ldg(bias_table + __ldg(rel_index + rem) * 6 + hg * 3 + hh)
                + __ldg(mask + (size_t)w * 2401 + rem);
    }
    __syncthreads();

    for (int t = warp; t < 12; t += 8) {
        const int h = t >> 2;
        const int sub = t & 3;
        const int jp = sub >> 1, ih = sub & 1;
        const int j = jp * 32 + lane;
        const bool jv = (j < 49);
        const int jc = jv ? j : 48;
        const float* krow = sk + (h * 49 + jc) * 36;
        float4 kreg[8];
        #pragma unroll
        for (int d4 = 0; d4 < 8; ++d4)
            kreg[d4] = *reinterpret_cast<const float4*>(krow + d4 * 4);
        const int i0 = ih * 25;
        const int i1 = ih ? 49 : 25;
        for (int i = i0; i < i1; ++i) {
            const float4* qp = sq4 + (h * 49 + i) * 8;
            float s = 0.f;
            #pragma unroll
            for (int d4 = 0; d4 < 8; ++d4) {
                const float4 q = qp[d4];
                s += q.x * kreg[d4].x + q.y * kreg[d4].y
                   + q.z * kreg[d4].z + q.w * kreg[d4].w;
            }
            if (jv) sa[(h * 49 + i) * 49 + j] += s;
        }
    }
    __syncthreads();

    if (tid < 147) {
        float* p = sa + tid * 49;
        float m = -1e30f;
        #pragma unroll 7
        for (int j = 0; j < 49; ++j) m = fmaxf(m, p[j]);
        float sum = 0.f;
        #pragma unroll 7
        for (int j = 0; j < 49; ++j) { const float e = __expf(p[j] - m); p[j] = e; sum += e; }
        const float inv = __frcp_rn(sum);
        #pragma unroll 7
        for (int j = 0; j < 49; ++j) p[j] *= inv;
    }
    __syncthreads();

    for (int t = warp; t < 12; t += 8) {
        const int h = t >> 2;
        const int dq = t & 3;
        const int ia = lane, ib = lane + 32;
        const bool bv = (ib < 49);
        const int ibc = bv ? ib : 48;
        const float* apa = sa + (h * 49 + ia) * 49;
        const float* apb = sa + (h * 49 + ibc) * 49;
        float4 A0 = {0,0,0,0}, A1 = {0,0,0,0}, B0 = {0,0,0,0}, B1 = {0,0,0,0};
        for (int j = 0; j < 49; ++j) {
            const float va = apa[j];
            const float vb = apb[j];
            const float4 v0 = sv4[(h * 49 + j) * 8 + dq * 2];
            const float4 v1 = sv4[(h * 49 + j) * 8 + dq * 2 + 1];
            A0.x += va * v0.x; A0.y += va * v0.y; A0.z += va * v0.z; A0.w += va * v0.w;
            A1.x += va * v1.x; A1.y += va * v1.y; A1.z += va * v1.z; A1.w += va * v1.w;
            B0.x += vb * v0.x; B0.y += vb * v0.y; B0.z += vb * v0.z; B0.w += vb * v0.w;
            B1.x += vb * v1.x; B1.y += vb * v1.y; B1.z += vb * v1.z; B1.w += vb * v1.w;
        }
        const int cb = h * 8 + dq * 2;
        so4[ia * 25 + cb]     = A0;
        so4[ia * 25 + cb + 1] = A1;
        if (bv) {
            so4[ib * 25 + cb]     = B0;
            so4[ib * 25 + cb + 1] = B1;
        }
    }
    __syncthreads();

    for (int idx = tid; idx < 49 * 24; idx += 256) {
        const int i = idx / 24;
        const int c4 = idx - i * 24;
        *reinterpret_cast<float4*>(&g_buf_so[((size_t)win * 49 + i) * 192 + hg * 96 + c4 * 4]) =
            so4[i * 25 + c4];
    }
}

// ---------------- wa_proj ----------------
__global__ __launch_bounds__(GT, 1)
void wa_proj(const float* __restrict__ proj_b, float* __restrict__ out) {
    extern __shared__ char smem[];
    const uint32_t sb = smem_u32(smem);
    const int tid = threadIdx.x;
    const int warp = tid >> 5, lane = tid & 31;
    const int wm = warp & 7, wn = warp >> 3;
    const int mtile = blockIdx.x;
    const int g = lane >> 2, tg = lane & 3;

    fetch_w(g_pw_hi, g_pw_lo, 0, sb + B_BUF0, sb + B_BUF0 + 25600, tid);
    CP_COMMIT();
    stage_act(g_buf_so + (size_t)mtile * 128 * 192, smem + A_HI, smem + A_LO, tid);

    const uint32_t aoff = (uint32_t)(wm * 16 + (lane & 15)) * 400u + ((lane >> 4) & 1) * 16u;
    const uint32_t boff = (uint32_t)(wn * 32 + (lane & 7) + ((lane >> 4) & 1) * 8) * 400u
                        + ((lane >> 3) & 1) * 16u;
    const uint32_t ahi = sb + A_HI + aoff;
    const uint32_t alo = sb + A_LO + aoff;

    for (int nt = 0; nt < 3; ++nt) {
        const uint32_t bbase = sb + B_BUF0 + (nt & 1) * B_BUF_SZ;
        if (nt + 1 < 3) {
            const uint32_t nb = sb + B_BUF0 + ((nt + 1) & 1) * B_BUF_SZ;
            fetch_w(g_pw_hi, g_pw_lo, nt + 1, nb, nb + 25600, tid);
            CP_COMMIT();
            CP_WAIT(1);
        } else {
            CP_WAIT(0);
        }
        __syncthreads();

        float c[4][4];
        #pragma unroll
        for (int i = 0; i < 4; ++i) { c[i][0] = 0.f; c[i][1] = 0.f; c[i][2] = 0.f; c[i][3] = 0.f; }

        warp_mma(c, ahi, alo, bbase + boff, bbase + 25600 + boff);

        const size_t mbase = (size_t)mtile * 128 + wm * 16;
        #pragma unroll
        for (int p2 = 0; p2 < 2; ++p2) {
            #pragma unroll
            for (int half = 0; half < 2; ++half) {
                const float* cc = c[2 * p2 + half];
                const int n = nt * 64 + wn * 32 + p2 * 16 + half * 8 + tg * 2;
                const float b0 = __ldg(proj_b + n);
                const float b1 = __ldg(proj_b + n + 1);
                *reinterpret_cast<float2*>(&out[(mbase + g) * 192 + n]) =
                    make_float2(cc[0] + b0, cc[1] + b1);
                *reinterpret_cast<float2*>(&out[(mbase + g + 8) * 192 + n]) =
                    make_float2(cc[2] + b0, cc[3] + b1);
            }
        }
        __syncthreads();
    }
}

extern "C" void kernel_launch(void* const* d_in, const int* in_sizes, int n_in,
                              void* d_out, int out_size) {
    const float* x          = (const float*)d_in[0];
    const float* mask       = (const float*)d_in[1];
    const float* qkv_w      = (const float*)d_in[2];
    const float* qkv_b      = (const float*)d_in[3];
    const float* proj_w     = (const float*)d_in[4];
    const float* proj_b     = (const float*)d_in[5];
    const float* bias_table = (const float*)d_in[6];
    const int*   rel_index  = (const int*)d_in[7];
    (void)in_sizes; (void)n_in; (void)out_size;

    cudaFuncSetAttribute(wa_qkv,  cudaFuncAttributeMaxDynamicSharedMemorySize, GEMM_SMEM);
    cudaFuncSetAttribute(wa_proj, cudaFuncAttributeMaxDynamicSharedMemorySize, GEMM_SMEM);
    cudaFuncSetAttribute(wa_attn, cudaFuncAttributeMaxDynamicSharedMemorySize, ATTN_FLOATS * 4);

    wa_prep<<<432, 256>>>(qkv_w, proj_w);
    wa_qkv<<<1568, GT, GEMM_SMEM>>>(x, qkv_b);
    wa_attn<<<8192, 256, ATTN_FLOATS * 4>>>(mask, bias_table, rel_index);
    wa_proj<<<1568, GT, GEMM_SMEM>>>(proj_b, (float*)d_out);
}

// round 16
// speedup vs baseline: 1.4141x; 1.0019x over previous
#include <cuda_runtime.h>
#include <cuda_bf16.h>
#include <cstdint>

// WindowAttention v15: R11 design with the misaligned-so4 bug fixed (AO 21903->21904).
// wa_prep -> wa_qkv -> wa_attn -> wa_proj

namespace {
constexpr int MTOT = 200704;
constexpr float QSCALE = 0.17677669529663687f;

constexpr int A_HI = 0;                       // 128 x 400 B
constexpr int A_LO = 51200;
constexpr int B_BUF0 = 102400;
constexpr int B_BUF_SZ = 51200;
constexpr int GEMM_SMEM = 204800;
constexpr int GT = 512;

constexpr int AQ = 0;                         // [3][49][32]
constexpr int AK = 4704;                      // [3][49][36]
constexpr int AV = 9996;                      // [3][49][32]
constexpr int AS = 14700;                     // [3][49][49] = 7203
constexpr int AO = 21904;                     // [49][100]  (16B-aligned float4 base!)
constexpr int ATTN_FLOATS = 26804;            // 107216 B
static_assert(AO % 4 == 0 && AV % 4 == 0 && AK % 4 == 0, "float4 bases must be 16B aligned");
}

__device__ __align__(16) float g_buf_qkv[(size_t)MTOT * 576];
__device__ __align__(16) float g_buf_so[(size_t)MTOT * 192];
__device__ __align__(16) unsigned short g_qw_hi[576 * 192];
__device__ __align__(16) unsigned short g_qw_lo[576 * 192];
__device__ __align__(16) unsigned short g_pw_hi[192 * 192];
__device__ __align__(16) unsigned short g_pw_lo[192 * 192];

__device__ __forceinline__ uint32_t smem_u32(const void* p) {
    uint32_t a;
    asm("{ .reg .u64 t; cvta.to.shared.u64 t, %1; cvt.u32.u64 %0, t; }" : "=r"(a) : "l"(p));
    return a;
}
__device__ __forceinline__ void cp16(uint32_t dst, const void* src) {
    asm volatile("cp.async.cg.shared.global [%0], [%1], 16;" :: "r"(dst), "l"(src));
}
#define CP_COMMIT() asm volatile("cp.async.commit_group;" ::: "memory")
#define CP_WAIT(n)  asm volatile("cp.async.wait_group %0;" :: "n"(n) : "memory")

__device__ __forceinline__ void ldmx4(uint32_t& r0, uint32_t& r1, uint32_t& r2, uint32_t& r3,
                                      uint32_t addr) {
    asm volatile("ldmatrix.sync.aligned.m8n8.x4.shared.b16 {%0,%1,%2,%3}, [%4];"
                 : "=r"(r0), "=r"(r1), "=r"(r2), "=r"(r3) : "r"(addr));
}
__device__ __forceinline__ void mma16816(float* c, uint32_t a0, uint32_t a1, uint32_t a2,
                                         uint32_t a3, uint32_t b0, uint32_t b1) {
    asm volatile("mma.sync.aligned.m16n8k16.row.col.f32.bf16.bf16.f32 "
                 "{%0,%1,%2,%3}, {%4,%5,%6,%7}, {%8,%9}, {%0,%1,%2,%3};"
                 : "+f"(c[0]), "+f"(c[1]), "+f"(c[2]), "+f"(c[3])
                 : "r"(a0), "r"(a1), "r"(a2), "r"(a3), "r"(b0), "r"(b1));
}

__device__ __forceinline__ void stage_act(const float* __restrict__ gsrc,
                                          char* shi, char* slo, int tid) {
    for (int p = tid; p < 128 * 96; p += GT) {
        const int r = p / 96;
        const int kp = p - r * 96;
        const float2 v = *reinterpret_cast<const float2*>(gsrc + (size_t)r * 192 + 2 * kp);
        const __nv_bfloat16 h0 = __float2bfloat16(v.x);
        const __nv_bfloat16 h1 = __float2bfloat16(v.y);
        const __nv_bfloat16 l0 = __float2bfloat16(v.x - __bfloat162float(h0));
        const __nv_bfloat16 l1 = __float2bfloat16(v.y - __bfloat162float(h1));
        const uint32_t hi = ((uint32_t)__bfloat16_as_ushort(h1) << 16) | __bfloat16_as_ushort(h0);
        const uint32_t lo = ((uint32_t)__bfloat16_as_ushort(l1) << 16) | __bfloat16_as_ushort(l0);
        const uint32_t off = (uint32_t)r * 400u + (uint32_t)kp * 4u;
        *reinterpret_cast<uint32_t*>(shi + off) = hi;
        *reinterpret_cast<uint32_t*>(slo + off) = lo;
    }
}

__device__ __forceinline__ void fetch_w(const unsigned short* wh, const unsigned short* wl,
                                        int nt, uint32_t dhi, uint32_t dlo, int tid) {
    for (int c = tid; c < 64 * 24; c += GT) {
        const int r = c / 24;
        const int k = c - r * 24;
        const uint32_t d = (uint32_t)r * 400u + (uint32_t)k * 16u;
        cp16(dhi + d, (const char*)(wh + (size_t)(nt * 64 + r) * 192) + k * 16);
        cp16(dlo + d, (const char*)(wl + (size_t)(nt * 64 + r) * 192) + k * 16);
    }
}

__device__ __forceinline__ void warp_mma(float (*c)[4], uint32_t ahi, uint32_t alo,
                                         uint32_t bhi, uint32_t blo) {
    #pragma unroll
    for (int ks = 0; ks < 12; ++ks) {
        uint32_t ah0, ah1, ah2, ah3, al0, al1, al2, al3;
        ldmx4(ah0, ah1, ah2, ah3, ahi + ks * 32);
        ldmx4(al0, al1, al2, al3, alo + ks * 32);
        #pragma unroll
        for (int p2 = 0; p2 < 2; ++p2) {
            uint32_t bh0, bh1, bh2, bh3, bl0, bl1, bl2, bl3;
            ldmx4(bh0, bh1, bh2, bh3, bhi + p2 * 6400 + ks * 32);
            ldmx4(bl0, bl1, bl2, bl3, blo + p2 * 6400 + ks * 32);
            mma16816(c[2 * p2],     ah0, ah1, ah2, ah3, bh0, bh1);
            mma16816(c[2 * p2 + 1], ah0, ah1, ah2, ah3, bh2, bh3);
            mma16816(c[2 * p2],     ah0, ah1, ah2, ah3, bl0, bl1);
            mma16816(c[2 * p2 + 1], ah0, ah1, ah2, ah3, bl2, bl3);
            mma16816(c[2 * p2],     al0, al1, al2, al3, bh0, bh1);
            mma16816(c[2 * p2 + 1], al0, al1, al2, al3, bh2, bh3);
        }
    }
}

// ---------------- wa_prep ----------------
__global__ __launch_bounds__(256)
void wa_prep(const float* __restrict__ qkv_w, const float* __restrict__ proj_w) {
    const int idx = blockIdx.x * 256 + threadIdx.x;
    if (idx < 576 * 192) {
        const float v = qkv_w[idx];
        const __nv_bfloat16 h = __float2bfloat16(v);
        g_qw_hi[idx] = __bfloat16_as_ushort(h);
        g_qw_lo[idx] = __bfloat16_as_ushort(__float2bfloat16(v - __bfloat162float(h)));
    }
    if (idx < 192 * 192) {
        const float v = proj_w[idx];
        const __nv_bfloat16 h = __float2bfloat16(v);
        g_pw_hi[idx] = __bfloat16_as_ushort(h);
        g_pw_lo[idx] = __bfloat16_as_ushort(__float2bfloat16(v - __bfloat162float(h)));
    }
}

// ---------------- wa_qkv ----------------
__global__ __launch_bounds__(GT, 1)
void wa_qkv(const float* __restrict__ x, const float* __restrict__ qkv_b) {
    extern __shared__ char smem[];
    const uint32_t sb = smem_u32(smem);
    const int tid = threadIdx.x;
    const int warp = tid >> 5, lane = tid & 31;
    const int wm = warp & 7, wn = warp >> 3;
    const int mtile = blockIdx.x;
    const int g = lane >> 2, tg = lane & 3;

    fetch_w(g_qw_hi, g_qw_lo, 0, sb + B_BUF0, sb + B_BUF0 + 25600, tid);
    CP_COMMIT();
    stage_act(x + (size_t)mtile * 128 * 192, smem + A_HI, smem + A_LO, tid);

    const uint32_t aoff = (uint32_t)(wm * 16 + (lane & 15)) * 400u + ((lane >> 4) & 1) * 16u;
    const uint32_t boff = (uint32_t)(wn * 32 + (lane & 7) + ((lane >> 4) & 1) * 8) * 400u
                        + ((lane >> 3) & 1) * 16u;
    const uint32_t ahi = sb + A_HI + aoff;
    const uint32_t alo = sb + A_LO + aoff;

    for (int nt = 0; nt < 9; ++nt) {
        const uint32_t bbase = sb + B_BUF0 + (nt & 1) * B_BUF_SZ;
        if (nt + 1 < 9) {
            const uint32_t nb = sb + B_BUF0 + ((nt + 1) & 1) * B_BUF_SZ;
            fetch_w(g_qw_hi, g_qw_lo, nt + 1, nb, nb + 25600, tid);
            CP_COMMIT();
            CP_WAIT(1);
        } else {
            CP_WAIT(0);
        }
        __syncthreads();

        float c[4][4];
        #pragma unroll
        for (int i = 0; i < 4; ++i) { c[i][0] = 0.f; c[i][1] = 0.f; c[i][2] = 0.f; c[i][3] = 0.f; }

        warp_mma(c, ahi, alo, bbase + boff, bbase + 25600 + boff);

        const size_t mbase = (size_t)mtile * 128 + wm * 16;
        #pragma unroll
        for (int p2 = 0; p2 < 2; ++p2) {
            #pragma unroll
            for (int half = 0; half < 2; ++half) {
                const float* cc = c[2 * p2 + half];
                const int n = nt * 64 + wn * 32 + p2 * 16 + half * 8 + tg * 2;
                const float b0 = __ldg(qkv_b + n);
                const float b1 = __ldg(qkv_b + n + 1);
                const float s = (n < 192) ? QSCALE : 1.f;
                *reinterpret_cast<float2*>(&g_buf_qkv[(mbase + g) * 576 + n]) =
                    make_float2((cc[0] + b0) * s, (cc[1] + b1) * s);
                *reinterpret_cast<float2*>(&g_buf_qkv[(mbase + g + 8) * 576 + n]) =
                    make_float2((cc[2] + b0) * s, (cc[3] + b1) * s);
            }
        }
        __syncthreads();
    }
}

// ---------------- wa_attn ----------------
__global__ __launch_bounds__(256, 2)
void wa_attn(const float* __restrict__ mask,
             const float* __restrict__ bias_table,
             const int* __restrict__ rel_index) {
    extern __shared__ float sf[];
    float* sq = sf + AQ;
    float* sk = sf + AK;
    float* sv = sf + AV;
    float* sa = sf + AS;
    float4* sq4 = reinterpret_cast<float4*>(sq);
    float4* sv4 = reinterpret_cast<float4*>(sv);
    float4* so4 = reinterpret_cast<float4*>(sf + AO);

    const int tid = threadIdx.x;
    const int warp = tid >> 5, lane = tid & 31;
    const int win = blockIdx.x >> 1;
    const int hg  = blockIdx.x & 1;
    const int w   = win & 63;

    for (int idx = tid; idx < 3 * 3 * 49 * 8; idx += 256) {
        const int mat = idx / (3 * 49 * 8);
        int rem = idx - mat * (3 * 49 * 8);
        const int h = rem / (49 * 8);
        rem -= h * (49 * 8);
        const int tok = rem >> 3;
        const int d4 = rem & 7;
        const float4 v = __ldg(reinterpret_cast<const float4*>(
            &g_buf_qkv[((size_t)win * 49 + tok) * 576 + mat * 192 + (hg * 3 + h) * 32 + d4 * 4]));
        if (mat == 0)      sq4[(h * 49 + tok) * 8 + d4] = v;
        else if (mat == 1) *reinterpret_cast<float4*>(sk + (h * 49 + tok) * 36 + d4 * 4) = v;
        else               sv4[(h * 49 + tok) * 8 + d4] = v;
    }
    for (int idx = tid; idx < 3 * 2401; idx += 256) {
        const int hh = idx / 2401;
        const int rem = idx - hh * 2401;
        sa[idx] = __ldg(bias_table + __ldg(rel_index + rem) * 6 + hg * 3 + hh)
                + __ldg(mask + (size_t)w * 2401 + rem);
    }
    __syncthreads();

    for (int t = warp; t < 12; t += 8) {
        const int h = t >> 2;
        const int sub = t & 3;
        const int jp = sub >> 1, ih = sub & 1;
        const int j = jp * 32 + lane;
        const bool jv = (j < 49);
        const int jc = jv ? j : 48;
        const float* krow = sk + (h * 49 + jc) * 36;
        float4 kreg[8];
        #pragma unroll
        for (int d4 = 0; d4 < 8; ++d4)
            kreg[d4] = *reinterpret_cast<const float4*>(krow + d4 * 4);
        const int i0 = ih * 25;
        const int i1 = ih ? 49 : 25;
        for (int i = i0; i < i1; ++i) {
            const float4* qp = sq4 + (h * 49 + i) * 8;
            float s = 0.f;
            #pragma unroll
            for (int d4 = 0; d4 < 8; ++d4) {
                const float4 q = qp[d4];
                s += q.x * kreg[d4].x + q.y * kreg[d4].y
                   + q.z * kreg[d4].z + q.w * kreg[d4].w;
            }
            if (jv) sa[(h * 49 + i) * 49 + j] += s;
        }
    }
    __syncthreads();

    if (tid < 147) {
        float* p = sa + tid * 49;
        float m = -1e30f;
        #pragma unroll 7
        for (int j = 0; j < 49; ++j) m = fmaxf(m, p[j]);
        float sum = 0.f;
        #pragma unroll 7
        for (int j = 0; j < 49; ++j) { const float e = __expf(p[j] - m); p[j] = e; sum += e; }
        const float inv = __frcp_rn(sum);
        #pragma unroll 7
        for (int j = 0; j < 49; ++j) p[j] *= inv;
    }
    __syncthreads();

    for (int t = warp; t < 12; t += 8) {
        const int h = t >> 2;
        const int dq = t & 3;
        const int ia = lane, ib = lane + 32;
        const bool bv = (ib < 49);
        const int ibc = bv ? ib : 48;
        const float* apa = sa + (h * 49 + ia) * 49;
        const float* apb = sa + (h * 49 + ibc) * 49;
        float4 A0 = {0,0,0,0}, A1 = {0,0,0,0}, B0 = {0,0,0,0}, B1 = {0,0,0,0};
        for (int j = 0; j < 49; ++j) {
            const float va = apa[j];
            const float vb = apb[j];
            const float4 v0 = sv4[(h * 49 + j) * 8 + dq * 2];
            const float4 v1 = sv4[(h * 49 + j) * 8 + dq * 2 + 1];
            A0.x += va * v0.x; A0.y += va * v0.y; A0.z += va * v0.z; A0.w += va * v0.w;
            A1.x += va * v1.x; A1.y += va * v1.y; A1.z += va * v1.z; A1.w += va * v1.w;
            B0.x += vb * v0.x; B0.y += vb * v0.y; B0.z += vb * v0.z; B0.w += vb * v0.w;
            B1.x += vb * v1.x; B1.y += vb * v1.y; B1.z += vb * v1.z; B1.w += vb * v1.w;
        }
        const int cb = h * 8 + dq * 2;
        so4[ia * 25 + cb]     = A0;
        so4[ia * 25 + cb + 1] = A1;
        if (bv) {
            so4[ib * 25 + cb]     = B0;
            so4[ib * 25 + cb + 1] = B1;
        }
    }
    __syncthreads();

    for (int idx = tid; idx < 49 * 24; idx += 256) {
        const int i = idx / 24;
        const int c4 = idx - i * 24;
        *reinterpret_cast<float4*>(&g_buf_so[((size_t)win * 49 + i) * 192 + hg * 96 + c4 * 4]) =
            so4[i * 25 + c4];
    }
}

// ---------------- wa_proj ----------------
__global__ __launch_bounds__(GT, 1)
void wa_proj(const float* __restrict__ proj_b, float* __restrict__ out) {
    extern __shared__ char smem[];
    const uint32_t sb = smem_u32(smem);
    const int tid = threadIdx.x;
    const int warp = tid >> 5, lane = tid & 31;
    const int wm = warp & 7, wn = warp >> 3;
    const int mtile = blockIdx.x;
    const int g = lane >> 2, tg = lane & 3;

    fetch_w(g_pw_hi, g_pw_lo, 0, sb + B_BUF0, sb + B_BUF0 + 25600, tid);
    CP_COMMIT();
    stage_act(g_buf_so + (size_t)mtile * 128 * 192, smem + A_HI, smem + A_LO, tid);

    const uint32_t aoff = (uint32_t)(wm * 16 + (lane & 15)) * 400u + ((lane >> 4) & 1) * 16u;
    const uint32_t boff = (uint32_t)(wn * 32 + (lane & 7) + ((lane >> 4) & 1) * 8) * 400u
                        + ((lane >> 3) & 1) * 16u;
    const uint32_t ahi = sb + A_HI + aoff;
    const uint32_t alo = sb + A_LO + aoff;

    for (int nt = 0; nt < 3; ++nt) {
        const uint32_t bbase = sb + B_BUF0 + (nt & 1) * B_BUF_SZ;
        if (nt + 1 < 3) {
            const uint32_t nb = sb + B_BUF0 + ((nt + 1) & 1) * B_BUF_SZ;
            fetch_w(g_pw_hi, g_pw_lo, nt + 1, nb, nb + 25600, tid);
            CP_COMMIT();
            CP_WAIT(1);
        } else {
            CP_WAIT(0);
        }
        __syncthreads();

        float c[4][4];
        #pragma unroll
        for (int i = 0; i < 4; ++i) { c[i][0] = 0.f; c[i][1] = 0.f; c[i][2] = 0.f; c[i][3] = 0.f; }

        warp_mma(c, ahi, alo, bbase + boff, bbase + 25600 + boff);

        const size_t mbase = (size_t)mtile * 128 + wm * 16;
        #pragma unroll
        for (int p2 = 0; p2 < 2; ++p2) {
            #pragma unroll
            for (int half = 0; half < 2; ++half) {
                const float* cc = c[2 * p2 + half];
                const int n = nt * 64 + wn * 32 + p2 * 16 + half * 8 + tg * 2;
                const float b0 = __ldg(proj_b + n);
                const float b1 = __ldg(proj_b + n + 1);
                *reinterpret_cast<float2*>(&out[(mbase + g) * 192 + n]) =
                    make_float2(cc[0] + b0, cc[1] + b1);
                *reinterpret_cast<float2*>(&out[(mbase + g + 8) * 192 + n]) =
                    make_float2(cc[2] + b0, cc[3] + b1);
            }
        }
        __syncthreads();
    }
}

extern "C" void kernel_launch(void* const* d_in, const int* in_sizes, int n_in,
                              void* d_out, int out_size) {
    const float* x          = (const float*)d_in[0];
    const float* mask       = (const float*)d_in[1];
    const float* qkv_w      = (const float*)d_in[2];
    const float* qkv_b      = (const float*)d_in[3];
    const float* proj_w     = (const float*)d_in[4];
    const float* proj_b     = (const float*)d_in[5];
    const float* bias_table = (const float*)d_in[6];
    const int*   rel_index  = (const int*)d_in[7];
    (void)in_sizes; (void)n_in; (void)out_size;

    cudaFuncSetAttribute(wa_qkv,  cudaFuncAttributeMaxDynamicSharedMemorySize, GEMM_SMEM);
    cudaFuncSetAttribute(wa_proj, cudaFuncAttributeMaxDynamicSharedMemorySize, GEMM_SMEM);
    cudaFuncSetAttribute(wa_attn, cudaFuncAttributeMaxDynamicSharedMemorySize, ATTN_FLOATS * 4);

    wa_prep<<<432, 256>>>(qkv_w, proj_w);
    wa_qkv<<<1568, GT, GEMM_SMEM>>>(x, qkv_b);
    wa_attn<<<8192, 256, ATTN_FLOATS * 4>>>(mask, bias_table, rel_index);
    wa_proj<<<1568, GT, GEMM_SMEM>>>(proj_b, (float*)d_out);
}